// round 13
// baseline (speedup 1.0000x reference)
#include <cuda_runtime.h>

#define Bb 64
#define Cc 256
#define Hh 64
#define Ww 64
#define Ss (Hh*Ww)   // 4096
#define HID 16
#define CSPLIT 4     // channel split for k1
#define K3C 8        // channels per block in k3

// scratch (no allocations allowed) — zero-initialized, self-resetting
__device__ float g_zp[CSPLIT][Bb*Ss];   // partial channel-contracted logits
__device__ float g_attn[Bb*Ss];         // softmax attention
__device__ float g_y[Bb*Cc];            // attention-pooled features
__device__ float g_gate[Bb*Cc];         // SE gate
__device__ unsigned int g_cnt[Bb];      // per-batch completion counters

// ---------------------------------------------------------------------------
// K1: zp[p][b][s] = sum_{c in chunk p} x[b][c][s] * conv_w[c]
// grid = Bb * 8 * CSPLIT = 2048 blocks (single wave), 128 threads, one float4
// per thread. Single accumulator + unroll-8: ptxas front-batches 8 LDG.128.
// ---------------------------------------------------------------------------
__global__ void k1_channel_dot(const float* __restrict__ x,
                               const float* __restrict__ conv_w) {
    int blk = blockIdx.x;
    int p = blk & (CSPLIT - 1);                 // channel chunk
    int sc = (blk >> 2) & 7;                    // spatial chunk
    int b = blk >> 5;                           // batch
    int c0 = p * (Cc / CSPLIT);

    __shared__ float wsh[Cc / CSPLIT];
    if (threadIdx.x < Cc / CSPLIT)
        wsh[threadIdx.x] = conv_w[c0 + threadIdx.x];
    __syncthreads();

    int s4 = (sc << 7) + threadIdx.x;           // float4 index in [0,1024)
    const float4* x4 = reinterpret_cast<const float4*>(
        x + (size_t)b * Cc * Ss + (size_t)c0 * Ss) + s4;

    float4 acc = make_float4(0.f, 0.f, 0.f, 0.f);
#pragma unroll 8
    for (int c = 0; c < Cc / CSPLIT; c++) {
        float w = wsh[c];
        float4 v = x4[(size_t)c * (Ss / 4)];
        acc.x = fmaf(v.x, w, acc.x);
        acc.y = fmaf(v.y, w, acc.y);
        acc.z = fmaf(v.z, w, acc.z);
        acc.w = fmaf(v.w, w, acc.w);
    }
    reinterpret_cast<float4*>(g_zp[p] + (size_t)b * Ss)[s4] = acc;
}

// ---------------------------------------------------------------------------
// K2: sum partials + 3x3x3 avg pool (zero pad, /27) + bias + softmax
// one block per batch (64 blocks, 256 threads)
// ---------------------------------------------------------------------------
__global__ void k2_pool_softmax(const float* __restrict__ conv_b) {
    __shared__ float zs[Ss];
    __shared__ float red[32];

    int b = blockIdx.x;
    int g = b >> 3;
    int t = b & 7;
    int tlo = (t > 0) ? t - 1 : 0;
    int thi = (t < 7) ? t + 1 : 7;

    {
        float4* zs4 = reinterpret_cast<float4*>(zs);
#pragma unroll
        for (int i = threadIdx.x; i < Ss / 4; i += 256) {
            float4 v = make_float4(0.f, 0.f, 0.f, 0.f);
            for (int tt = tlo; tt <= thi; tt++) {
#pragma unroll
                for (int p = 0; p < CSPLIT; p++) {
                    float4 u = reinterpret_cast<const float4*>(
                        g_zp[p] + (g * 8 + tt) * Ss)[i];
                    v.x += u.x; v.y += u.y; v.z += u.z; v.w += u.w;
                }
            }
            zs4[i] = v;
        }
    }
    __syncthreads();

    const float cb = conv_b[0];
    float lg[16];
    float lmax = -1e30f;
#pragma unroll
    for (int i = 0; i < 16; i++) {
        int s = threadIdx.x + (i << 8);
        int h = s >> 6, w = s & 63;
        float sum = 0.f;
#pragma unroll
        for (int dh = -1; dh <= 1; dh++) {
            int hh = h + dh;
            if (hh < 0 || hh >= Hh) continue;
#pragma unroll
            for (int dw = -1; dw <= 1; dw++) {
                int ww = w + dw;
                if (ww < 0 || ww >= Ww) continue;
                sum += zs[(hh << 6) + ww];
            }
        }
        float l = sum * (1.f / 27.f) + cb;
        lg[i] = l;
        lmax = fmaxf(lmax, l);
    }

    for (int o = 16; o; o >>= 1) lmax = fmaxf(lmax, __shfl_xor_sync(0xffffffffu, lmax, o));
    if ((threadIdx.x & 31) == 0) red[threadIdx.x >> 5] = lmax;
    __syncthreads();
    if (threadIdx.x < 32) {
        float v = (threadIdx.x < 8) ? red[threadIdx.x] : -1e30f;
        for (int o = 4; o; o >>= 1) v = fmaxf(v, __shfl_xor_sync(0xffffffffu, v, o));
        if (threadIdx.x == 0) red[0] = v;
    }
    __syncthreads();
    lmax = red[0];
    __syncthreads();

    float lsum = 0.f;
#pragma unroll
    for (int i = 0; i < 16; i++) {
        lg[i] = expf(lg[i] - lmax);
        lsum += lg[i];
    }
    for (int o = 16; o; o >>= 1) lsum += __shfl_xor_sync(0xffffffffu, lsum, o);
    if ((threadIdx.x & 31) == 0) red[threadIdx.x >> 5] = lsum;
    __syncthreads();
    if (threadIdx.x < 32) {
        float v = (threadIdx.x < 8) ? red[threadIdx.x] : 0.f;
        for (int o = 4; o; o >>= 1) v += __shfl_xor_sync(0xffffffffu, v, o);
        if (threadIdx.x == 0) red[0] = v;
    }
    __syncthreads();
    float inv = 1.f / red[0];
#pragma unroll
    for (int i = 0; i < 16; i++) {
        int s = threadIdx.x + (i << 8);
        g_attn[b * Ss + s] = lg[i] * inv;
    }
}

// ---------------------------------------------------------------------------
// K3 v3 (proven): attn staged in smem once per block, 8 channels per block
// (warp w owns channel c0+w), dot loop bounded to unroll-4 (no spills).
// Fused SE-MLP tail on the last-finishing block of each batch.
// grid = Bb * (Cc/K3C) = 2048 blocks, 256 threads (8 warps)
// ---------------------------------------------------------------------------
__global__ void __launch_bounds__(256) k3_weighted_pool_mlp(
        const float* __restrict__ x,
        const float* __restrict__ fc1,
        const float* __restrict__ fc2) {
    __shared__ float4 attn_s[Ss / 4];      // 16 KB
    __shared__ unsigned int s_old;

    int blk = blockIdx.x;
    int b = blk >> 5;                       // 32 blocks per batch
    int c0 = (blk & 31) * K3C;
    int tid = threadIdx.x;
    int warp = tid >> 5, lane = tid & 31;

    // stage attn[b] into smem (4 float4 per thread)
    {
        const float4* a4 = reinterpret_cast<const float4*>(g_attn + (size_t)b * Ss);
#pragma unroll
        for (int j = 0; j < 4; j++)
            attn_s[tid + (j << 8)] = a4[tid + (j << 8)];
    }
    __syncthreads();

    // warp `warp` dots channel c0+warp against smem attn (bounded unroll)
    int c = c0 + warp;
    const float4* x4 = reinterpret_cast<const float4*>(
        x + ((size_t)b * Cc + c) * Ss);
    float acc = 0.f;
#pragma unroll 4
    for (int i = 0; i < (Ss / 4) / 32; i++) {
        int idx = lane + (i << 5);
        float4 v = __ldcs(&x4[idx]);
        float4 a = attn_s[idx];
        acc += v.x * a.x + v.y * a.y + v.z * a.z + v.w * a.w;
    }
    for (int o = 16; o; o >>= 1) acc += __shfl_xor_sync(0xffffffffu, acc, o);
    if (lane == 0) g_y[b * Cc + c] = acc;
    __syncthreads();
    if (tid == 0) {
        __threadfence();
        s_old = atomicAdd(&g_cnt[b], 1u);
    }
    __syncthreads();

    if (s_old == (Cc / K3C) - 1) {
        // last block of batch b: run the SE MLP
        __shared__ float ys[Cc];
        __shared__ float hs[HID];
        if (tid < Cc) ys[tid] = __ldcg(&g_y[b * Cc + tid]);
        __syncthreads();

        // 8 warps x 2 hid units each
#pragma unroll
        for (int u = 0; u < 2; u++) {
            int h = (warp << 1) + u;
            float a = 0.f;
#pragma unroll
            for (int i = 0; i < Cc / 32; i++) {
                int cc = lane + (i << 5);
                a = fmaf(ys[cc], fc1[h * Cc + cc], a);
            }
            for (int o = 16; o; o >>= 1) a += __shfl_xor_sync(0xffffffffu, a, o);
            if (lane == 0) hs[h] = fmaxf(a, 0.f);
        }
        __syncthreads();
        if (tid < Cc) {
            float a = 0.f;
            const float* w2 = fc2 + tid * HID;
#pragma unroll
            for (int j = 0; j < HID; j++) a = fmaf(hs[j], w2[j], a);
            g_gate[b * Cc + tid] = 1.f / (1.f + expf(-a));
        }
        if (tid == 0) g_cnt[b] = 0;   // reset for next graph replay
    }
}

// ---------------------------------------------------------------------------
// K5 v2 (proven): out = x * gate[b,c]. 4 float4 per thread, front-batched
// loads, streaming loads+stores. One (b,c) row per block -> gate uniform.
// grid = 16384 blocks, 256 threads. 73.9us @ 82% DRAM busy (6.5 TB/s).
// ---------------------------------------------------------------------------
__global__ void __launch_bounds__(256) k5_scale(const float* __restrict__ x,
                                                float* __restrict__ out) {
    int bc = blockIdx.x;                    // one block per (b,c) row
    int tid = threadIdx.x;
    float gv = g_gate[bc];

    const float4* x4 = reinterpret_cast<const float4*>(x + (size_t)bc * Ss);
    float4* o4 = reinterpret_cast<float4*>(out + (size_t)bc * Ss);

    float4 v0 = __ldcs(&x4[tid]);
    float4 v1 = __ldcs(&x4[tid + 256]);
    float4 v2 = __ldcs(&x4[tid + 512]);
    float4 v3 = __ldcs(&x4[tid + 768]);
    v0.x *= gv; v0.y *= gv; v0.z *= gv; v0.w *= gv;
    v1.x *= gv; v1.y *= gv; v1.z *= gv; v1.w *= gv;
    v2.x *= gv; v2.y *= gv; v2.z *= gv; v2.w *= gv;
    v3.x *= gv; v3.y *= gv; v3.z *= gv; v3.w *= gv;
    __stcs(&o4[tid], v0);
    __stcs(&o4[tid + 256], v1);
    __stcs(&o4[tid + 512], v2);
    __stcs(&o4[tid + 768], v3);
}

// ---------------------------------------------------------------------------
extern "C" void kernel_launch(void* const* d_in, const int* in_sizes, int n_in,
                              void* d_out, int out_size) {
    const float* x      = (const float*)d_in[0];
    const float* conv_w = (const float*)d_in[1];
    const float* conv_b = (const float*)d_in[2];
    const float* fc1_w  = (const float*)d_in[3];
    const float* fc2_w  = (const float*)d_in[4];
    float* out = (float*)d_out;

    k1_channel_dot<<<Bb * 8 * CSPLIT, 128>>>(x, conv_w);
    k2_pool_softmax<<<Bb, 256>>>(conv_b);
    k3_weighted_pool_mlp<<<Bb * (Cc / K3C), 256>>>(x, fc1_w, fc2_w);
    k5_scale<<<Bb * Cc, 256>>>(x, out);
}

// round 14
// speedup vs baseline: 1.0152x; 1.0152x over previous
#include <cuda_runtime.h>

#define Bb 64
#define Cc 256
#define Hh 64
#define Ww 64
#define Ss (Hh*Ww)   // 4096
#define HID 16
#define CSPLIT 4     // channel split for k1
#define K3C 8        // channels per block in k3

// scratch (no allocations allowed) — zero-initialized, self-resetting
__device__ float g_zp[CSPLIT][Bb*Ss];   // partial channel-contracted logits
__device__ float g_attn[Bb*Ss];         // softmax attention
__device__ float g_y[Bb*Cc];            // attention-pooled features
__device__ float g_gate[Bb*Cc];         // SE gate
__device__ unsigned int g_cnt[Bb];      // per-batch completion counters

// ---------------------------------------------------------------------------
// K1: zp[p][b][s] = sum_{c in chunk p} x[b][c][s] * conv_w[c]
// grid = Bb * 8 * CSPLIT = 2048 blocks (single wave), 128 threads, one float4
// per thread. Single accumulator + unroll-8: ptxas front-batches 8 LDG.128.
// ---------------------------------------------------------------------------
__global__ void k1_channel_dot(const float* __restrict__ x,
                               const float* __restrict__ conv_w) {
    int blk = blockIdx.x;
    int p = blk & (CSPLIT - 1);                 // channel chunk
    int sc = (blk >> 2) & 7;                    // spatial chunk
    int b = blk >> 5;                           // batch
    int c0 = p * (Cc / CSPLIT);

    __shared__ float wsh[Cc / CSPLIT];
    if (threadIdx.x < Cc / CSPLIT)
        wsh[threadIdx.x] = conv_w[c0 + threadIdx.x];
    __syncthreads();

    int s4 = (sc << 7) + threadIdx.x;           // float4 index in [0,1024)
    const float4* x4 = reinterpret_cast<const float4*>(
        x + (size_t)b * Cc * Ss + (size_t)c0 * Ss) + s4;

    float4 acc = make_float4(0.f, 0.f, 0.f, 0.f);
#pragma unroll 8
    for (int c = 0; c < Cc / CSPLIT; c++) {
        float w = wsh[c];
        float4 v = x4[(size_t)c * (Ss / 4)];
        acc.x = fmaf(v.x, w, acc.x);
        acc.y = fmaf(v.y, w, acc.y);
        acc.z = fmaf(v.z, w, acc.z);
        acc.w = fmaf(v.w, w, acc.w);
    }
    reinterpret_cast<float4*>(g_zp[p] + (size_t)b * Ss)[s4] = acc;
}

// ---------------------------------------------------------------------------
// K2 v2: sum partials + 3x3x3 avg pool (zero pad, /27) + bias + softmax.
// one block per batch, 1024 threads (vs 256): per-thread serial chain 16->4,
// staging loop 4 iters -> 1. Same 16KB smem tile, reduction tree over 32 warps.
// ---------------------------------------------------------------------------
__global__ void __launch_bounds__(1024) k2_pool_softmax(
        const float* __restrict__ conv_b) {
    __shared__ float zs[Ss];
    __shared__ float red[32];

    int b = blockIdx.x;
    int g = b >> 3;
    int t = b & 7;
    int tlo = (t > 0) ? t - 1 : 0;
    int thi = (t < 7) ? t + 1 : 7;
    int tid = threadIdx.x;
    int warp = tid >> 5, lane = tid & 31;

    // t-sum + partial-sum staging: one float4 per thread (1024 x float4 = Ss)
    {
        float4 v = make_float4(0.f, 0.f, 0.f, 0.f);
        for (int tt = tlo; tt <= thi; tt++) {
#pragma unroll
            for (int p = 0; p < CSPLIT; p++) {
                float4 u = reinterpret_cast<const float4*>(
                    g_zp[p] + (g * 8 + tt) * Ss)[tid];
                v.x += u.x; v.y += u.y; v.z += u.z; v.w += u.w;
            }
        }
        reinterpret_cast<float4*>(zs)[tid] = v;
    }
    __syncthreads();

    const float cb = conv_b[0];
    float lg[4];
    float lmax = -1e30f;
#pragma unroll
    for (int i = 0; i < 4; i++) {
        int s = tid + (i << 10);
        int h = s >> 6, w = s & 63;
        float sum = 0.f;
#pragma unroll
        for (int dh = -1; dh <= 1; dh++) {
            int hh = h + dh;
            if (hh < 0 || hh >= Hh) continue;
#pragma unroll
            for (int dw = -1; dw <= 1; dw++) {
                int ww = w + dw;
                if (ww < 0 || ww >= Ww) continue;
                sum += zs[(hh << 6) + ww];
            }
        }
        float l = sum * (1.f / 27.f) + cb;
        lg[i] = l;
        lmax = fmaxf(lmax, l);
    }

    // block max over 32 warps
    for (int o = 16; o; o >>= 1) lmax = fmaxf(lmax, __shfl_xor_sync(0xffffffffu, lmax, o));
    if (lane == 0) red[warp] = lmax;
    __syncthreads();
    if (tid < 32) {
        float v = red[tid];
        for (int o = 16; o; o >>= 1) v = fmaxf(v, __shfl_xor_sync(0xffffffffu, v, o));
        if (tid == 0) red[0] = v;
    }
    __syncthreads();
    lmax = red[0];
    __syncthreads();   // protect red[] before reuse

    float lsum = 0.f;
#pragma unroll
    for (int i = 0; i < 4; i++) {
        lg[i] = expf(lg[i] - lmax);
        lsum += lg[i];
    }
    for (int o = 16; o; o >>= 1) lsum += __shfl_xor_sync(0xffffffffu, lsum, o);
    if (lane == 0) red[warp] = lsum;
    __syncthreads();
    if (tid < 32) {
        float v = red[tid];
        for (int o = 16; o; o >>= 1) v += __shfl_xor_sync(0xffffffffu, v, o);
        if (tid == 0) red[0] = v;
    }
    __syncthreads();
    float inv = 1.f / red[0];
#pragma unroll
    for (int i = 0; i < 4; i++) {
        int s = tid + (i << 10);
        g_attn[b * Ss + s] = lg[i] * inv;
    }
}

// ---------------------------------------------------------------------------
// K3 v3 (proven): attn staged in smem once per block, 8 channels per block
// (warp w owns channel c0+w), dot loop bounded to unroll-4 (no spills).
// Fused SE-MLP tail on the last-finishing block of each batch.
// grid = Bb * (Cc/K3C) = 2048 blocks, 256 threads (8 warps)
// ---------------------------------------------------------------------------
__global__ void __launch_bounds__(256) k3_weighted_pool_mlp(
        const float* __restrict__ x,
        const float* __restrict__ fc1,
        const float* __restrict__ fc2) {
    __shared__ float4 attn_s[Ss / 4];      // 16 KB
    __shared__ unsigned int s_old;

    int blk = blockIdx.x;
    int b = blk >> 5;                       // 32 blocks per batch
    int c0 = (blk & 31) * K3C;
    int tid = threadIdx.x;
    int warp = tid >> 5, lane = tid & 31;

    // stage attn[b] into smem (4 float4 per thread)
    {
        const float4* a4 = reinterpret_cast<const float4*>(g_attn + (size_t)b * Ss);
#pragma unroll
        for (int j = 0; j < 4; j++)
            attn_s[tid + (j << 8)] = a4[tid + (j << 8)];
    }
    __syncthreads();

    // warp `warp` dots channel c0+warp against smem attn (bounded unroll)
    int c = c0 + warp;
    const float4* x4 = reinterpret_cast<const float4*>(
        x + ((size_t)b * Cc + c) * Ss);
    float acc = 0.f;
#pragma unroll 4
    for (int i = 0; i < (Ss / 4) / 32; i++) {
        int idx = lane + (i << 5);
        float4 v = __ldcs(&x4[idx]);
        float4 a = attn_s[idx];
        acc += v.x * a.x + v.y * a.y + v.z * a.z + v.w * a.w;
    }
    for (int o = 16; o; o >>= 1) acc += __shfl_xor_sync(0xffffffffu, acc, o);
    if (lane == 0) g_y[b * Cc + c] = acc;
    __syncthreads();
    if (tid == 0) {
        __threadfence();
        s_old = atomicAdd(&g_cnt[b], 1u);
    }
    __syncthreads();

    if (s_old == (Cc / K3C) - 1) {
        // last block of batch b: run the SE MLP
        __shared__ float ys[Cc];
        __shared__ float hs[HID];
        if (tid < Cc) ys[tid] = __ldcg(&g_y[b * Cc + tid]);
        __syncthreads();

        // 8 warps x 2 hid units each
#pragma unroll
        for (int u = 0; u < 2; u++) {
            int h = (warp << 1) + u;
            float a = 0.f;
#pragma unroll
            for (int i = 0; i < Cc / 32; i++) {
                int cc = lane + (i << 5);
                a = fmaf(ys[cc], fc1[h * Cc + cc], a);
            }
            for (int o = 16; o; o >>= 1) a += __shfl_xor_sync(0xffffffffu, a, o);
            if (lane == 0) hs[h] = fmaxf(a, 0.f);
        }
        __syncthreads();
        if (tid < Cc) {
            float a = 0.f;
            const float* w2 = fc2 + tid * HID;
#pragma unroll
            for (int j = 0; j < HID; j++) a = fmaf(hs[j], w2[j], a);
            g_gate[b * Cc + tid] = 1.f / (1.f + expf(-a));
        }
        if (tid == 0) g_cnt[b] = 0;   // reset for next graph replay
    }
}

// ---------------------------------------------------------------------------
// K5 v2 (proven): out = x * gate[b,c]. 4 float4 per thread, front-batched
// loads, streaming loads+stores. One (b,c) row per block -> gate uniform.
// grid = 16384 blocks, 256 threads. ~74us @ ~82% DRAM busy (6.5 TB/s).
// ---------------------------------------------------------------------------
__global__ void __launch_bounds__(256) k5_scale(const float* __restrict__ x,
                                                float* __restrict__ out) {
    int bc = blockIdx.x;                    // one block per (b,c) row
    int tid = threadIdx.x;
    float gv = g_gate[bc];

    const float4* x4 = reinterpret_cast<const float4*>(x + (size_t)bc * Ss);
    float4* o4 = reinterpret_cast<float4*>(out + (size_t)bc * Ss);

    float4 v0 = __ldcs(&x4[tid]);
    float4 v1 = __ldcs(&x4[tid + 256]);
    float4 v2 = __ldcs(&x4[tid + 512]);
    float4 v3 = __ldcs(&x4[tid + 768]);
    v0.x *= gv; v0.y *= gv; v0.z *= gv; v0.w *= gv;
    v1.x *= gv; v1.y *= gv; v1.z *= gv; v1.w *= gv;
    v2.x *= gv; v2.y *= gv; v2.z *= gv; v2.w *= gv;
    v3.x *= gv; v3.y *= gv; v3.z *= gv; v3.w *= gv;
    __stcs(&o4[tid], v0);
    __stcs(&o4[tid + 256], v1);
    __stcs(&o4[tid + 512], v2);
    __stcs(&o4[tid + 768], v3);
}

// ---------------------------------------------------------------------------
extern "C" void kernel_launch(void* const* d_in, const int* in_sizes, int n_in,
                              void* d_out, int out_size) {
    const float* x      = (const float*)d_in[0];
    const float* conv_w = (const float*)d_in[1];
    const float* conv_b = (const float*)d_in[2];
    const float* fc1_w  = (const float*)d_in[3];
    const float* fc2_w  = (const float*)d_in[4];
    float* out = (float*)d_out;

    k1_channel_dot<<<Bb * 8 * CSPLIT, 128>>>(x, conv_w);
    k2_pool_softmax<<<Bb, 1024>>>(conv_b);
    k3_weighted_pool_mlp<<<Bb * (Cc / K3C), 256>>>(x, fc1_w, fc2_w);
    k5_scale<<<Bb * Cc, 256>>>(x, out);
}

// round 15
// speedup vs baseline: 1.0164x; 1.0012x over previous
#include <cuda_runtime.h>

#define Bb 64
#define Cc 256
#define Hh 64
#define Ww 64
#define Ss (Hh*Ww)   // 4096
#define HID 16
#define CSPLIT 4     // channel split for k1
#define K3C 8        // channels per block in k3

// scratch (no allocations allowed) — zero-initialized, self-resetting
__device__ float g_zp[CSPLIT][Bb*Ss];   // partial channel-contracted logits
__device__ float g_attn[Bb*Ss];         // softmax attention
__device__ float g_y[Bb*Cc];            // attention-pooled features
__device__ float g_gate[Bb*Cc];         // SE gate
__device__ unsigned int g_cnt[Bb];      // per-batch completion counters

// ---------------------------------------------------------------------------
// K1: zp[p][b][s] = sum_{c in chunk p} x[b][c][s] * conv_w[c]
// grid = Bb * 8 * CSPLIT = 2048 blocks (single wave), 128 threads, one float4
// per thread. Single accumulator + unroll-8: ptxas front-batches 8 LDG.128.
// (Do NOT restructure ILP here — dual-accumulator variant regressed, R10.)
// ---------------------------------------------------------------------------
__global__ void k1_channel_dot(const float* __restrict__ x,
                               const float* __restrict__ conv_w) {
    int blk = blockIdx.x;
    int p = blk & (CSPLIT - 1);                 // channel chunk
    int sc = (blk >> 2) & 7;                    // spatial chunk
    int b = blk >> 5;                           // batch
    int c0 = p * (Cc / CSPLIT);

    __shared__ float wsh[Cc / CSPLIT];
    if (threadIdx.x < Cc / CSPLIT)
        wsh[threadIdx.x] = conv_w[c0 + threadIdx.x];
    __syncthreads();

    int s4 = (sc << 7) + threadIdx.x;           // float4 index in [0,1024)
    const float4* x4 = reinterpret_cast<const float4*>(
        x + (size_t)b * Cc * Ss + (size_t)c0 * Ss) + s4;

    float4 acc = make_float4(0.f, 0.f, 0.f, 0.f);
#pragma unroll 8
    for (int c = 0; c < Cc / CSPLIT; c++) {
        float w = wsh[c];
        float4 v = x4[(size_t)c * (Ss / 4)];
        acc.x = fmaf(v.x, w, acc.x);
        acc.y = fmaf(v.y, w, acc.y);
        acc.z = fmaf(v.z, w, acc.z);
        acc.w = fmaf(v.w, w, acc.w);
    }
    reinterpret_cast<float4*>(g_zp[p] + (size_t)b * Ss)[s4] = acc;
}

// ---------------------------------------------------------------------------
// K2 v2 (proven R14): sum partials + 3x3x3 avg pool (zero pad, /27) + bias +
// softmax. One block per batch, 1024 threads: per-thread serial chain = 4,
// staging = 1 float4/thread. 16KB smem tile, reduction tree over 32 warps.
// ---------------------------------------------------------------------------
__global__ void __launch_bounds__(1024) k2_pool_softmax(
        const float* __restrict__ conv_b) {
    __shared__ float zs[Ss];
    __shared__ float red[32];

    int b = blockIdx.x;
    int g = b >> 3;
    int t = b & 7;
    int tlo = (t > 0) ? t - 1 : 0;
    int thi = (t < 7) ? t + 1 : 7;
    int tid = threadIdx.x;
    int warp = tid >> 5, lane = tid & 31;

    // t-sum + partial-sum staging: one float4 per thread (1024 x float4 = Ss)
    {
        float4 v = make_float4(0.f, 0.f, 0.f, 0.f);
        for (int tt = tlo; tt <= thi; tt++) {
#pragma unroll
            for (int p = 0; p < CSPLIT; p++) {
                float4 u = reinterpret_cast<const float4*>(
                    g_zp[p] + (g * 8 + tt) * Ss)[tid];
                v.x += u.x; v.y += u.y; v.z += u.z; v.w += u.w;
            }
        }
        reinterpret_cast<float4*>(zs)[tid] = v;
    }
    __syncthreads();

    const float cb = conv_b[0];
    float lg[4];
    float lmax = -1e30f;
#pragma unroll
    for (int i = 0; i < 4; i++) {
        int s = tid + (i << 10);
        int h = s >> 6, w = s & 63;
        float sum = 0.f;
#pragma unroll
        for (int dh = -1; dh <= 1; dh++) {
            int hh = h + dh;
            if (hh < 0 || hh >= Hh) continue;
#pragma unroll
            for (int dw = -1; dw <= 1; dw++) {
                int ww = w + dw;
                if (ww < 0 || ww >= Ww) continue;
                sum += zs[(hh << 6) + ww];
            }
        }
        float l = sum * (1.f / 27.f) + cb;
        lg[i] = l;
        lmax = fmaxf(lmax, l);
    }

    // block max over 32 warps
    for (int o = 16; o; o >>= 1) lmax = fmaxf(lmax, __shfl_xor_sync(0xffffffffu, lmax, o));
    if (lane == 0) red[warp] = lmax;
    __syncthreads();
    if (tid < 32) {
        float v = red[tid];
        for (int o = 16; o; o >>= 1) v = fmaxf(v, __shfl_xor_sync(0xffffffffu, v, o));
        if (tid == 0) red[0] = v;
    }
    __syncthreads();
    lmax = red[0];
    __syncthreads();   // protect red[] before reuse

    float lsum = 0.f;
#pragma unroll
    for (int i = 0; i < 4; i++) {
        lg[i] = expf(lg[i] - lmax);
        lsum += lg[i];
    }
    for (int o = 16; o; o >>= 1) lsum += __shfl_xor_sync(0xffffffffu, lsum, o);
    if (lane == 0) red[warp] = lsum;
    __syncthreads();
    if (tid < 32) {
        float v = red[tid];
        for (int o = 16; o; o >>= 1) v += __shfl_xor_sync(0xffffffffu, v, o);
        if (tid == 0) red[0] = v;
    }
    __syncthreads();
    float inv = 1.f / red[0];
#pragma unroll
    for (int i = 0; i < 4; i++) {
        int s = tid + (i << 10);
        g_attn[b * Ss + s] = lg[i] * inv;
    }
}

// ---------------------------------------------------------------------------
// K3 v3 (proven): attn staged in smem once per block, 8 channels per block
// (warp w owns channel c0+w), dot loop bounded to unroll-4 (no spills —
// full unroll regressed, R6). Fused SE-MLP tail on the last-finishing block
// of each batch (removes the separate k4 launch).
// grid = Bb * (Cc/K3C) = 2048 blocks, 256 threads (8 warps)
// ---------------------------------------------------------------------------
__global__ void __launch_bounds__(256) k3_weighted_pool_mlp(
        const float* __restrict__ x,
        const float* __restrict__ fc1,
        const float* __restrict__ fc2) {
    __shared__ float4 attn_s[Ss / 4];      // 16 KB
    __shared__ unsigned int s_old;

    int blk = blockIdx.x;
    int b = blk >> 5;                       // 32 blocks per batch
    int c0 = (blk & 31) * K3C;
    int tid = threadIdx.x;
    int warp = tid >> 5, lane = tid & 31;

    // stage attn[b] into smem (4 float4 per thread)
    {
        const float4* a4 = reinterpret_cast<const float4*>(g_attn + (size_t)b * Ss);
#pragma unroll
        for (int j = 0; j < 4; j++)
            attn_s[tid + (j << 8)] = a4[tid + (j << 8)];
    }
    __syncthreads();

    // warp `warp` dots channel c0+warp against smem attn (bounded unroll)
    int c = c0 + warp;
    const float4* x4 = reinterpret_cast<const float4*>(
        x + ((size_t)b * Cc + c) * Ss);
    float acc = 0.f;
#pragma unroll 4
    for (int i = 0; i < (Ss / 4) / 32; i++) {
        int idx = lane + (i << 5);
        float4 v = __ldcs(&x4[idx]);
        float4 a = attn_s[idx];
        acc += v.x * a.x + v.y * a.y + v.z * a.z + v.w * a.w;
    }
    for (int o = 16; o; o >>= 1) acc += __shfl_xor_sync(0xffffffffu, acc, o);
    if (lane == 0) g_y[b * Cc + c] = acc;
    __syncthreads();
    if (tid == 0) {
        __threadfence();
        s_old = atomicAdd(&g_cnt[b], 1u);
    }
    __syncthreads();

    if (s_old == (Cc / K3C) - 1) {
        // last block of batch b: run the SE MLP
        __shared__ float ys[Cc];
        __shared__ float hs[HID];
        if (tid < Cc) ys[tid] = __ldcg(&g_y[b * Cc + tid]);
        __syncthreads();

        // 8 warps x 2 hid units each
#pragma unroll
        for (int u = 0; u < 2; u++) {
            int h = (warp << 1) + u;
            float a = 0.f;
#pragma unroll
            for (int i = 0; i < Cc / 32; i++) {
                int cc = lane + (i << 5);
                a = fmaf(ys[cc], fc1[h * Cc + cc], a);
            }
            for (int o = 16; o; o >>= 1) a += __shfl_xor_sync(0xffffffffu, a, o);
            if (lane == 0) hs[h] = fmaxf(a, 0.f);
        }
        __syncthreads();
        if (tid < Cc) {
            float a = 0.f;
            const float* w2 = fc2 + tid * HID;
#pragma unroll
            for (int j = 0; j < HID; j++) a = fmaf(hs[j], w2[j], a);
            g_gate[b * Cc + tid] = 1.f / (1.f + expf(-a));
        }
        if (tid == 0) g_cnt[b] = 0;   // reset for next graph replay
    }
}

// ---------------------------------------------------------------------------
// K5 v2 (proven): out = x * gate[b,c]. 4 float4 per thread (depth-4 is the
// measured MLP optimum — depth 8 regressed, R9), front-batched loads,
// streaming loads+stores. One (b,c) row per block -> gate uniform.
// grid = 16384 blocks, 256 threads. ~74-75us @ ~81% DRAM busy (6.4-6.5 TB/s).
// ---------------------------------------------------------------------------
__global__ void __launch_bounds__(256) k5_scale(const float* __restrict__ x,
                                                float* __restrict__ out) {
    int bc = blockIdx.x;                    // one block per (b,c) row
    int tid = threadIdx.x;
    float gv = g_gate[bc];

    const float4* x4 = reinterpret_cast<const float4*>(x + (size_t)bc * Ss);
    float4* o4 = reinterpret_cast<float4*>(out + (size_t)bc * Ss);

    float4 v0 = __ldcs(&x4[tid]);
    float4 v1 = __ldcs(&x4[tid + 256]);
    float4 v2 = __ldcs(&x4[tid + 512]);
    float4 v3 = __ldcs(&x4[tid + 768]);
    v0.x *= gv; v0.y *= gv; v0.z *= gv; v0.w *= gv;
    v1.x *= gv; v1.y *= gv; v1.z *= gv; v1.w *= gv;
    v2.x *= gv; v2.y *= gv; v2.z *= gv; v2.w *= gv;
    v3.x *= gv; v3.y *= gv; v3.z *= gv; v3.w *= gv;
    __stcs(&o4[tid], v0);
    __stcs(&o4[tid + 256], v1);
    __stcs(&o4[tid + 512], v2);
    __stcs(&o4[tid + 768], v3);
}

// ---------------------------------------------------------------------------
extern "C" void kernel_launch(void* const* d_in, const int* in_sizes, int n_in,
                              void* d_out, int out_size) {
    const float* x      = (const float*)d_in[0];
    const float* conv_w = (const float*)d_in[1];
    const float* conv_b = (const float*)d_in[2];
    const float* fc1_w  = (const float*)d_in[3];
    const float* fc2_w  = (const float*)d_in[4];
    float* out = (float*)d_out;

    k1_channel_dot<<<Bb * 8 * CSPLIT, 128>>>(x, conv_w);
    k2_pool_softmax<<<Bb, 1024>>>(conv_b);
    k3_weighted_pool_mlp<<<Bb * (Cc / K3C), 256>>>(x, fc1_w, fc2_w);
    k5_scale<<<Bb * Cc, 256>>>(x, out);
}

// round 16
// speedup vs baseline: 1.0210x; 1.0045x over previous
#include <cuda_runtime.h>

#define Bb 64
#define Cc 256
#define Hh 64
#define Ww 64
#define Ss (Hh*Ww)   // 4096
#define HID 16
#define CSPLIT 4     // channel split for k1
#define K3C 8        // channels per block in k3

// scratch (no allocations allowed) — zero-initialized, self-resetting
__device__ float g_zp[CSPLIT][Bb*Ss];   // partial channel-contracted logits
__device__ float g_attn[Bb*Ss];         // softmax attention
__device__ float g_y[Bb*Cc];            // attention-pooled features
__device__ float g_gate[Bb*Cc];         // SE gate
__device__ unsigned int g_cnt[Bb];      // per-batch completion counters

// ---------------------------------------------------------------------------
// K1: zp[p][b][s] = sum_{c in chunk p} x[b][c][s] * conv_w[c]
// grid = Bb * 8 * CSPLIT = 2048 blocks (single wave), 128 threads, one float4
// per thread. Single accumulator + unroll-8: ptxas front-batches 8 LDG.128.
// (Do NOT restructure ILP here — dual-accumulator variant regressed, R10.)
// ---------------------------------------------------------------------------
__global__ void k1_channel_dot(const float* __restrict__ x,
                               const float* __restrict__ conv_w) {
    int blk = blockIdx.x;
    int p = blk & (CSPLIT - 1);                 // channel chunk
    int sc = (blk >> 2) & 7;                    // spatial chunk
    int b = blk >> 5;                           // batch
    int c0 = p * (Cc / CSPLIT);

    __shared__ float wsh[Cc / CSPLIT];
    if (threadIdx.x < Cc / CSPLIT)
        wsh[threadIdx.x] = conv_w[c0 + threadIdx.x];
    __syncthreads();

    int s4 = (sc << 7) + threadIdx.x;           // float4 index in [0,1024)
    const float4* x4 = reinterpret_cast<const float4*>(
        x + (size_t)b * Cc * Ss + (size_t)c0 * Ss) + s4;

    float4 acc = make_float4(0.f, 0.f, 0.f, 0.f);
#pragma unroll 8
    for (int c = 0; c < Cc / CSPLIT; c++) {
        float w = wsh[c];
        float4 v = x4[(size_t)c * (Ss / 4)];
        acc.x = fmaf(v.x, w, acc.x);
        acc.y = fmaf(v.y, w, acc.y);
        acc.z = fmaf(v.z, w, acc.z);
        acc.w = fmaf(v.w, w, acc.w);
    }
    reinterpret_cast<float4*>(g_zp[p] + (size_t)b * Ss)[s4] = acc;
}

// ---------------------------------------------------------------------------
// K2 v2 (proven R14): sum partials + 3x3x3 avg pool (zero pad, /27) + bias +
// softmax. One block per batch, 1024 threads: per-thread serial chain = 4,
// staging = 1 float4/thread. 16KB smem tile, reduction tree over 32 warps.
// ---------------------------------------------------------------------------
__global__ void __launch_bounds__(1024) k2_pool_softmax(
        const float* __restrict__ conv_b) {
    __shared__ float zs[Ss];
    __shared__ float red[32];

    int b = blockIdx.x;
    int g = b >> 3;
    int t = b & 7;
    int tlo = (t > 0) ? t - 1 : 0;
    int thi = (t < 7) ? t + 1 : 7;
    int tid = threadIdx.x;
    int warp = tid >> 5, lane = tid & 31;

    // t-sum + partial-sum staging: one float4 per thread (1024 x float4 = Ss)
    {
        float4 v = make_float4(0.f, 0.f, 0.f, 0.f);
        for (int tt = tlo; tt <= thi; tt++) {
#pragma unroll
            for (int p = 0; p < CSPLIT; p++) {
                float4 u = reinterpret_cast<const float4*>(
                    g_zp[p] + (g * 8 + tt) * Ss)[tid];
                v.x += u.x; v.y += u.y; v.z += u.z; v.w += u.w;
            }
        }
        reinterpret_cast<float4*>(zs)[tid] = v;
    }
    __syncthreads();

    const float cb = conv_b[0];
    float lg[4];
    float lmax = -1e30f;
#pragma unroll
    for (int i = 0; i < 4; i++) {
        int s = tid + (i << 10);
        int h = s >> 6, w = s & 63;
        float sum = 0.f;
#pragma unroll
        for (int dh = -1; dh <= 1; dh++) {
            int hh = h + dh;
            if (hh < 0 || hh >= Hh) continue;
#pragma unroll
            for (int dw = -1; dw <= 1; dw++) {
                int ww = w + dw;
                if (ww < 0 || ww >= Ww) continue;
                sum += zs[(hh << 6) + ww];
            }
        }
        float l = sum * (1.f / 27.f) + cb;
        lg[i] = l;
        lmax = fmaxf(lmax, l);
    }

    // block max over 32 warps
    for (int o = 16; o; o >>= 1) lmax = fmaxf(lmax, __shfl_xor_sync(0xffffffffu, lmax, o));
    if (lane == 0) red[warp] = lmax;
    __syncthreads();
    if (tid < 32) {
        float v = red[tid];
        for (int o = 16; o; o >>= 1) v = fmaxf(v, __shfl_xor_sync(0xffffffffu, v, o));
        if (tid == 0) red[0] = v;
    }
    __syncthreads();
    lmax = red[0];
    __syncthreads();   // protect red[] before reuse

    float lsum = 0.f;
#pragma unroll
    for (int i = 0; i < 4; i++) {
        lg[i] = expf(lg[i] - lmax);
        lsum += lg[i];
    }
    for (int o = 16; o; o >>= 1) lsum += __shfl_xor_sync(0xffffffffu, lsum, o);
    if (lane == 0) red[warp] = lsum;
    __syncthreads();
    if (tid < 32) {
        float v = red[tid];
        for (int o = 16; o; o >>= 1) v += __shfl_xor_sync(0xffffffffu, v, o);
        if (tid == 0) red[0] = v;
    }
    __syncthreads();
    float inv = 1.f / red[0];
#pragma unroll
    for (int i = 0; i < 4; i++) {
        int s = tid + (i << 10);
        g_attn[b * Ss + s] = lg[i] * inv;
    }
}

// ---------------------------------------------------------------------------
// K3 v3 (proven): attn staged in smem once per block, 8 channels per block
// (warp w owns channel c0+w), dot loop bounded to unroll-4 (no spills —
// full unroll regressed, R6). Fused SE-MLP tail on the last-finishing block
// of each batch (removes the separate k4 launch).
// grid = Bb * (Cc/K3C) = 2048 blocks, 256 threads (8 warps)
// ---------------------------------------------------------------------------
__global__ void __launch_bounds__(256) k3_weighted_pool_mlp(
        const float* __restrict__ x,
        const float* __restrict__ fc1,
        const float* __restrict__ fc2) {
    __shared__ float4 attn_s[Ss / 4];      // 16 KB
    __shared__ unsigned int s_old;

    int blk = blockIdx.x;
    int b = blk >> 5;                       // 32 blocks per batch
    int c0 = (blk & 31) * K3C;
    int tid = threadIdx.x;
    int warp = tid >> 5, lane = tid & 31;

    // stage attn[b] into smem (4 float4 per thread)
    {
        const float4* a4 = reinterpret_cast<const float4*>(g_attn + (size_t)b * Ss);
#pragma unroll
        for (int j = 0; j < 4; j++)
            attn_s[tid + (j << 8)] = a4[tid + (j << 8)];
    }
    __syncthreads();

    // warp `warp` dots channel c0+warp against smem attn (bounded unroll)
    int c = c0 + warp;
    const float4* x4 = reinterpret_cast<const float4*>(
        x + ((size_t)b * Cc + c) * Ss);
    float acc = 0.f;
#pragma unroll 4
    for (int i = 0; i < (Ss / 4) / 32; i++) {
        int idx = lane + (i << 5);
        float4 v = __ldcs(&x4[idx]);
        float4 a = attn_s[idx];
        acc += v.x * a.x + v.y * a.y + v.z * a.z + v.w * a.w;
    }
    for (int o = 16; o; o >>= 1) acc += __shfl_xor_sync(0xffffffffu, acc, o);
    if (lane == 0) g_y[b * Cc + c] = acc;
    __syncthreads();
    if (tid == 0) {
        __threadfence();
        s_old = atomicAdd(&g_cnt[b], 1u);
    }
    __syncthreads();

    if (s_old == (Cc / K3C) - 1) {
        // last block of batch b: run the SE MLP
        __shared__ float ys[Cc];
        __shared__ float hs[HID];
        if (tid < Cc) ys[tid] = __ldcg(&g_y[b * Cc + tid]);
        __syncthreads();

        // 8 warps x 2 hid units each
#pragma unroll
        for (int u = 0; u < 2; u++) {
            int h = (warp << 1) + u;
            float a = 0.f;
#pragma unroll
            for (int i = 0; i < Cc / 32; i++) {
                int cc = lane + (i << 5);
                a = fmaf(ys[cc], fc1[h * Cc + cc], a);
            }
            for (int o = 16; o; o >>= 1) a += __shfl_xor_sync(0xffffffffu, a, o);
            if (lane == 0) hs[h] = fmaxf(a, 0.f);
        }
        __syncthreads();
        if (tid < Cc) {
            float a = 0.f;
            const float* w2 = fc2 + tid * HID;
#pragma unroll
            for (int j = 0; j < HID; j++) a = fmaf(hs[j], w2[j], a);
            g_gate[b * Cc + tid] = 1.f / (1.f + expf(-a));
        }
        if (tid == 0) g_cnt[b] = 0;   // reset for next graph replay
    }
}

// ---------------------------------------------------------------------------
// K5 v2 (proven): out = x * gate[b,c]. 4 float4 per thread (depth-4 is the
// measured MLP optimum — depth 8 regressed, R9), front-batched loads,
// streaming loads+stores. One (b,c) row per block -> gate uniform.
// grid = 16384 blocks, 256 threads. ~74-75us @ ~81% DRAM busy (6.4-6.5 TB/s).
// ---------------------------------------------------------------------------
__global__ void __launch_bounds__(256) k5_scale(const float* __restrict__ x,
                                                float* __restrict__ out) {
    int bc = blockIdx.x;                    // one block per (b,c) row
    int tid = threadIdx.x;
    float gv = g_gate[bc];

    const float4* x4 = reinterpret_cast<const float4*>(x + (size_t)bc * Ss);
    float4* o4 = reinterpret_cast<float4*>(out + (size_t)bc * Ss);

    float4 v0 = __ldcs(&x4[tid]);
    float4 v1 = __ldcs(&x4[tid + 256]);
    float4 v2 = __ldcs(&x4[tid + 512]);
    float4 v3 = __ldcs(&x4[tid + 768]);
    v0.x *= gv; v0.y *= gv; v0.z *= gv; v0.w *= gv;
    v1.x *= gv; v1.y *= gv; v1.z *= gv; v1.w *= gv;
    v2.x *= gv; v2.y *= gv; v2.z *= gv; v2.w *= gv;
    v3.x *= gv; v3.y *= gv; v3.z *= gv; v3.w *= gv;
    __stcs(&o4[tid], v0);
    __stcs(&o4[tid + 256], v1);
    __stcs(&o4[tid + 512], v2);
    __stcs(&o4[tid + 768], v3);
}

// ---------------------------------------------------------------------------
extern "C" void kernel_launch(void* const* d_in, const int* in_sizes, int n_in,
                              void* d_out, int out_size) {
    const float* x      = (const float*)d_in[0];
    const float* conv_w = (const float*)d_in[1];
    const float* conv_b = (const float*)d_in[2];
    const float* fc1_w  = (const float*)d_in[3];
    const float* fc2_w  = (const float*)d_in[4];
    float* out = (float*)d_out;

    k1_channel_dot<<<Bb * 8 * CSPLIT, 128>>>(x, conv_w);
    k2_pool_softmax<<<Bb, 1024>>>(conv_b);
    k3_weighted_pool_mlp<<<Bb * (Cc / K3C), 256>>>(x, fc1_w, fc2_w);
    k5_scale<<<Bb * Cc, 256>>>(x, out);
}